// round 2
// baseline (speedup 1.0000x reference)
#include <cuda_runtime.h>
#include <math_constants.h>

// Problem constants (fixed by the reference setup)
#define BB   4
#define NN   32768
#define KK   16
#define DD   8
#define TOT  (BB * NN * KK)        // 2,097,152 elements per channel
#define GRPS (TOT / 4)             // 524,288 groups of 4 (along K)
#define TPB  256
#define NBLK (GRPS / TPB)          // 2048 blocks
#define EPSF 1e-6f

// Global accumulators for BatchNorm statistics (double for accuracy).
__device__ double g_sum[DD];
__device__ double g_sqs[DD];

__global__ void k_zero_stats() {
    if (threadIdx.x < DD) {
        g_sum[threadIdx.x] = 0.0;
        g_sqs[threadIdx.x] = 0.0;
    }
}

__device__ __forceinline__ int clamp_idx(int v) {
    v = v < 0 ? 0 : v;
    return v >= NN ? NN - 1 : v;
}

__global__ void __launch_bounds__(TPB) k_pass1_stats(
    const float* __restrict__ coords,      // (B,N,3)
    const int* __restrict__ knn_idx,       // (B,N,K) int32 (JAX x64 disabled)
    const float* __restrict__ knn_dist,    // (B,N,K)
    const int* __restrict__ mask,          // (B,N)
    const float* __restrict__ conv_w,      // (D,10)
    const float* __restrict__ conv_b)      // (D)
{
    const int g  = blockIdx.x * TPB + threadIdx.x;
    const int e0 = g * 4;
    const int b  = e0 / (NN * KK);
    const int rm = e0 - b * (NN * KK);
    const int n  = rm / KK;

    const float* cbat = coords + (size_t)b * NN * 3;
    const float cx = cbat[n * 3 + 0];
    const float cy = cbat[n * 3 + 1];
    const float cz = cbat[n * 3 + 2];

    // Folded weights: x = base[d] + wn·nbr + wd*dist
    float wn0[DD], wn1[DD], wn2[DD], wdd[DD], base[DD];
#pragma unroll
    for (int d = 0; d < DD; d++) {
        const float* w = conv_w + d * 10;
        float w0 = w[0], w1 = w[1], w2 = w[2];
        float w3 = w[3], w4 = w[4], w5 = w[5];
        float w6 = w[6], w7 = w[7], w8 = w[8];
        wn0[d] = w3 - w6; wn1[d] = w4 - w7; wn2[d] = w5 - w8;
        wdd[d] = w[9];
        base[d] = conv_b[d] + (w0 + w6) * cx + (w1 + w7) * cy + (w2 + w8) * cz;
    }

    // 4 neighbor indices (one LDG.128) + 4 distances (one LDG.128)
    int4 iv = *reinterpret_cast<const int4*>(knn_idx + e0);
    int j[4];
    j[0] = clamp_idx(iv.x);
    j[1] = clamp_idx(iv.y);
    j[2] = clamp_idx(iv.z);
    j[3] = clamp_idx(iv.w);

    float4 d4 = *reinterpret_cast<const float4*>(knn_dist + e0);
    float dv[4] = {d4.x, d4.y, d4.z, d4.w};
    if (mask[b * NN + n] == 0) {
        dv[0] = dv[1] = dv[2] = dv[3] = CUDART_INF_F;
    }

    // Gather neighbor coords (coords = 1.5 MB total, L2-resident)
    float nx[4], ny[4], nz[4];
#pragma unroll
    for (int i = 0; i < 4; i++) {
        const float* p = cbat + j[i] * 3;
        nx[i] = p[0]; ny[i] = p[1]; nz[i] = p[2];
    }

    float s[DD], q[DD];
#pragma unroll
    for (int d = 0; d < DD; d++) { s[d] = 0.f; q[d] = 0.f; }

#pragma unroll
    for (int i = 0; i < 4; i++) {
#pragma unroll
        for (int d = 0; d < DD; d++) {
            float x = base[d] + wn0[d] * nx[i] + wn1[d] * ny[i]
                    + wn2[d] * nz[i] + wdd[d] * dv[i];
            s[d] += x;
            q[d] = fmaf(x, x, q[d]);
        }
    }

    // Warp reduction (fp32), then block partials, then double atomics.
#pragma unroll
    for (int d = 0; d < DD; d++) {
#pragma unroll
        for (int o = 16; o > 0; o >>= 1) {
            s[d] += __shfl_xor_sync(0xFFFFFFFFu, s[d], o);
            q[d] += __shfl_xor_sync(0xFFFFFFFFu, q[d], o);
        }
    }

    __shared__ float sh[TPB / 32][2 * DD];
    const int warp = threadIdx.x >> 5;
    const int lane = threadIdx.x & 31;
    if (lane == 0) {
#pragma unroll
        for (int d = 0; d < DD; d++) {
            sh[warp][d]      = s[d];
            sh[warp][DD + d] = q[d];
        }
    }
    __syncthreads();
    if (threadIdx.x < 2 * DD) {
        float acc = 0.f;
#pragma unroll
        for (int w = 0; w < TPB / 32; w++) acc += sh[w][threadIdx.x];
        if (threadIdx.x < DD)
            atomicAdd(&g_sum[threadIdx.x], (double)acc);
        else
            atomicAdd(&g_sqs[threadIdx.x - DD], (double)acc);
    }
}

__global__ void __launch_bounds__(TPB) k_pass2_write(
    const float* __restrict__ coords,
    const float* __restrict__ features,    // (B,D,N,1)
    const int* __restrict__ knn_idx,
    const float* __restrict__ knn_dist,
    const int* __restrict__ mask,
    const float* __restrict__ conv_w,
    const float* __restrict__ conv_b,
    const float* __restrict__ bn_gamma,
    const float* __restrict__ bn_beta,
    float* __restrict__ out)               // (B, 2D, N, K)
{
    const int g  = blockIdx.x * TPB + threadIdx.x;
    const int e0 = g * 4;
    const int b  = e0 / (NN * KK);
    const int rm = e0 - b * (NN * KK);
    const int n  = rm / KK;
    const int k0 = rm - n * KK;

    // BatchNorm affine params from global double sums (pass1 ordered before us)
    float scale[DD], shift[DD];
#pragma unroll
    for (int d = 0; d < DD; d++) {
        double mean = g_sum[d] * (1.0 / (double)TOT);
        double var  = g_sqs[d] * (1.0 / (double)TOT) - mean * mean;
        float rstd  = rsqrtf((float)var + EPSF);
        float sc    = bn_gamma[d] * rstd;
        scale[d] = sc;
        shift[d] = bn_beta[d] - (float)mean * sc;
    }

    const float* cbat = coords + (size_t)b * NN * 3;
    const float cx = cbat[n * 3 + 0];
    const float cy = cbat[n * 3 + 1];
    const float cz = cbat[n * 3 + 2];

    float wn0[DD], wn1[DD], wn2[DD], wdd[DD], base[DD];
#pragma unroll
    for (int d = 0; d < DD; d++) {
        const float* w = conv_w + d * 10;
        float w0 = w[0], w1 = w[1], w2 = w[2];
        float w3 = w[3], w4 = w[4], w5 = w[5];
        float w6 = w[6], w7 = w[7], w8 = w[8];
        wn0[d] = w3 - w6; wn1[d] = w4 - w7; wn2[d] = w5 - w8;
        wdd[d] = w[9];
        base[d] = conv_b[d] + (w0 + w6) * cx + (w1 + w7) * cy + (w2 + w8) * cz;
    }

    int4 iv = *reinterpret_cast<const int4*>(knn_idx + e0);
    int j[4];
    j[0] = clamp_idx(iv.x);
    j[1] = clamp_idx(iv.y);
    j[2] = clamp_idx(iv.z);
    j[3] = clamp_idx(iv.w);

    float4 d4 = *reinterpret_cast<const float4*>(knn_dist + e0);
    float dv[4] = {d4.x, d4.y, d4.z, d4.w};
    if (mask[b * NN + n] == 0) {
        dv[0] = dv[1] = dv[2] = dv[3] = CUDART_INF_F;
    }

    float nx[4], ny[4], nz[4];
#pragma unroll
    for (int i = 0; i < 4; i++) {
        const float* p = cbat + j[i] * 3;
        nx[i] = p[0]; ny[i] = p[1]; nz[i] = p[2];
    }

    // Channels [0..7]: normalized + relu conv output, float4 stores along K
    const size_t obase = ((size_t)b * (2 * DD)) * NN * KK + (size_t)n * KK + k0;
#pragma unroll
    for (int d = 0; d < DD; d++) {
        float4 o;
        float x0 = base[d] + wn0[d]*nx[0] + wn1[d]*ny[0] + wn2[d]*nz[0] + wdd[d]*dv[0];
        float x1 = base[d] + wn0[d]*nx[1] + wn1[d]*ny[1] + wn2[d]*nz[1] + wdd[d]*dv[1];
        float x2 = base[d] + wn0[d]*nx[2] + wn1[d]*ny[2] + wn2[d]*nz[2] + wdd[d]*dv[2];
        float x3 = base[d] + wn0[d]*nx[3] + wn1[d]*ny[3] + wn2[d]*nz[3] + wdd[d]*dv[3];
        o.x = fmaxf(fmaf(x0, scale[d], shift[d]), 0.f);
        o.y = fmaxf(fmaf(x1, scale[d], shift[d]), 0.f);
        o.z = fmaxf(fmaf(x2, scale[d], shift[d]), 0.f);
        o.w = fmaxf(fmaf(x3, scale[d], shift[d]), 0.f);
        *reinterpret_cast<float4*>(out + obase + (size_t)d * NN * KK) = o;
    }

    // Channels [8..15]: broadcast input features along K
#pragma unroll
    for (int d = 0; d < DD; d++) {
        float fv = features[((size_t)b * DD + d) * NN + n];
        float4 o = {fv, fv, fv, fv};
        *reinterpret_cast<float4*>(out + obase + (size_t)(DD + d) * NN * KK) = o;
    }
}

extern "C" void kernel_launch(void* const* d_in, const int* in_sizes, int n_in,
                              void* d_out, int out_size) {
    const float* coords   = (const float*)d_in[0];
    const float* features = (const float*)d_in[1];
    const int*   knn_idx  = (const int*)d_in[2];
    const float* knn_dist = (const float*)d_in[3];
    const int*   mask     = (const int*)d_in[4];
    const float* conv_w   = (const float*)d_in[5];
    const float* conv_b   = (const float*)d_in[6];
    const float* bn_gamma = (const float*)d_in[7];
    const float* bn_beta  = (const float*)d_in[8];
    float*       out      = (float*)d_out;

    k_zero_stats<<<1, 32>>>();
    k_pass1_stats<<<NBLK, TPB>>>(coords, knn_idx, knn_dist, mask, conv_w, conv_b);
    k_pass2_write<<<NBLK, TPB>>>(coords, features, knn_idx, knn_dist, mask,
                                 conv_w, conv_b, bn_gamma, bn_beta, out);
}

// round 3
// speedup vs baseline: 1.0586x; 1.0586x over previous
#include <cuda_runtime.h>
#include <math_constants.h>

// Problem constants (fixed by the reference setup)
#define BB   4
#define NN   32768
#define KK   16
#define DD   8
#define TOT  (BB * NN * KK)        // 2,097,152 elements per channel
#define GRPS (TOT / 4)             // 524,288 groups of 4 (along K)
#define TPB  256
#define NBLK (GRPS / TPB)          // 2048 blocks
#define EPSF 1e-6f

// Global accumulators for BatchNorm statistics (double for accuracy).
__device__ double g_sum[DD];
__device__ double g_sqs[DD];
// Repacked coords: one float4 per point -> single LDG.128 gather.
__device__ float4 g_c4[BB * NN];

__device__ __forceinline__ int clamp_idx(int v) {
    v = v < 0 ? 0 : v;
    return v >= NN ? NN - 1 : v;
}

// Repack (B,N,3) coords -> float4 scratch; also zero the stats accumulators.
__global__ void __launch_bounds__(TPB) k_repack(const float* __restrict__ coords) {
    const int i = blockIdx.x * TPB + threadIdx.x;   // 0 .. BB*NN-1
    if (blockIdx.x == 0 && threadIdx.x < DD) {
        g_sum[threadIdx.x] = 0.0;
        g_sqs[threadIdx.x] = 0.0;
    }
    const float x = coords[3 * i + 0];
    const float y = coords[3 * i + 1];
    const float z = coords[3 * i + 2];
    g_c4[i] = make_float4(x, y, z, 0.f);
}

__global__ void __launch_bounds__(TPB) k_pass1_stats(
    const float* __restrict__ coords,      // (B,N,3)
    const int* __restrict__ knn_idx,       // (B,N,K) int32
    const float* __restrict__ knn_dist,    // (B,N,K)
    const int* __restrict__ mask,          // (B,N)
    const float* __restrict__ conv_w,      // (D,10)
    const float* __restrict__ conv_b)      // (D)
{
    const int g  = blockIdx.x * TPB + threadIdx.x;
    const int e0 = g * 4;
    const int b  = e0 / (NN * KK);
    const int rm = e0 - b * (NN * KK);
    const int n  = rm / KK;

    const float4 c = g_c4[b * NN + n];
    const float cx = c.x, cy = c.y, cz = c.z;

    // Folded weights: x = base[d] + wn·nbr + wd*dist
    float wn0[DD], wn1[DD], wn2[DD], wdd[DD], base[DD];
#pragma unroll
    for (int d = 0; d < DD; d++) {
        const float* w = conv_w + d * 10;
        float w0 = w[0], w1 = w[1], w2 = w[2];
        float w3 = w[3], w4 = w[4], w5 = w[5];
        float w6 = w[6], w7 = w[7], w8 = w[8];
        wn0[d] = w3 - w6; wn1[d] = w4 - w7; wn2[d] = w5 - w8;
        wdd[d] = w[9];
        base[d] = conv_b[d] + (w0 + w6) * cx + (w1 + w7) * cy + (w2 + w8) * cz;
    }

    // 4 neighbor indices (one LDG.128) + 4 distances (one LDG.128)
    int4 iv = *reinterpret_cast<const int4*>(knn_idx + e0);
    int j[4];
    j[0] = clamp_idx(iv.x);
    j[1] = clamp_idx(iv.y);
    j[2] = clamp_idx(iv.z);
    j[3] = clamp_idx(iv.w);

    float4 d4 = *reinterpret_cast<const float4*>(knn_dist + e0);
    float dv[4] = {d4.x, d4.y, d4.z, d4.w};
    if (mask[b * NN + n] == 0) {
        dv[0] = dv[1] = dv[2] = dv[3] = CUDART_INF_F;
    }

    // Gather neighbor coords: one LDG.128 each (repacked float4)
    float nx[4], ny[4], nz[4];
#pragma unroll
    for (int i = 0; i < 4; i++) {
        float4 p = g_c4[b * NN + j[i]];
        nx[i] = p.x; ny[i] = p.y; nz[i] = p.z;
    }

    float s[DD], q[DD];
#pragma unroll
    for (int d = 0; d < DD; d++) { s[d] = 0.f; q[d] = 0.f; }

#pragma unroll
    for (int i = 0; i < 4; i++) {
#pragma unroll
        for (int d = 0; d < DD; d++) {
            float x = base[d] + wn0[d] * nx[i] + wn1[d] * ny[i]
                    + wn2[d] * nz[i] + wdd[d] * dv[i];
            s[d] += x;
            q[d] = fmaf(x, x, q[d]);
        }
    }

    // Warp reduction (fp32), then block partials, then double atomics.
#pragma unroll
    for (int d = 0; d < DD; d++) {
#pragma unroll
        for (int o = 16; o > 0; o >>= 1) {
            s[d] += __shfl_xor_sync(0xFFFFFFFFu, s[d], o);
            q[d] += __shfl_xor_sync(0xFFFFFFFFu, q[d], o);
        }
    }

    __shared__ float sh[TPB / 32][2 * DD];
    const int warp = threadIdx.x >> 5;
    const int lane = threadIdx.x & 31;
    if (lane == 0) {
#pragma unroll
        for (int d = 0; d < DD; d++) {
            sh[warp][d]      = s[d];
            sh[warp][DD + d] = q[d];
        }
    }
    __syncthreads();
    if (threadIdx.x < 2 * DD) {
        float acc = 0.f;
#pragma unroll
        for (int w = 0; w < TPB / 32; w++) acc += sh[w][threadIdx.x];
        if (threadIdx.x < DD)
            atomicAdd(&g_sum[threadIdx.x], (double)acc);
        else
            atomicAdd(&g_sqs[threadIdx.x - DD], (double)acc);
    }
}

__global__ void __launch_bounds__(TPB) k_pass2_write(
    const float* __restrict__ coords,
    const float* __restrict__ features,    // (B,D,N,1)
    const int* __restrict__ knn_idx,
    const float* __restrict__ knn_dist,
    const int* __restrict__ mask,
    const float* __restrict__ conv_w,
    const float* __restrict__ conv_b,
    const float* __restrict__ bn_gamma,
    const float* __restrict__ bn_beta,
    float* __restrict__ out)               // (B, 2D, N, K)
{
    const int g  = blockIdx.x * TPB + threadIdx.x;
    const int e0 = g * 4;
    const int b  = e0 / (NN * KK);
    const int rm = e0 - b * (NN * KK);
    const int n  = rm / KK;
    const int k0 = rm - n * KK;

    // BatchNorm affine params from global double sums (pass1 ordered before us)
    float scale[DD], shift[DD];
#pragma unroll
    for (int d = 0; d < DD; d++) {
        double mean = g_sum[d] * (1.0 / (double)TOT);
        double var  = g_sqs[d] * (1.0 / (double)TOT) - mean * mean;
        float rstd  = rsqrtf((float)var + EPSF);
        float sc    = bn_gamma[d] * rstd;
        scale[d] = sc;
        shift[d] = bn_beta[d] - (float)mean * sc;
    }

    const float4 c = g_c4[b * NN + n];
    const float cx = c.x, cy = c.y, cz = c.z;

    float wn0[DD], wn1[DD], wn2[DD], wdd[DD], base[DD];
#pragma unroll
    for (int d = 0; d < DD; d++) {
        const float* w = conv_w + d * 10;
        float w0 = w[0], w1 = w[1], w2 = w[2];
        float w3 = w[3], w4 = w[4], w5 = w[5];
        float w6 = w[6], w7 = w[7], w8 = w[8];
        wn0[d] = w3 - w6; wn1[d] = w4 - w7; wn2[d] = w5 - w8;
        wdd[d] = w[9];
        base[d] = conv_b[d] + (w0 + w6) * cx + (w1 + w7) * cy + (w2 + w8) * cz;
    }

    int4 iv = *reinterpret_cast<const int4*>(knn_idx + e0);
    int j[4];
    j[0] = clamp_idx(iv.x);
    j[1] = clamp_idx(iv.y);
    j[2] = clamp_idx(iv.z);
    j[3] = clamp_idx(iv.w);

    float4 d4 = *reinterpret_cast<const float4*>(knn_dist + e0);
    float dv[4] = {d4.x, d4.y, d4.z, d4.w};
    if (mask[b * NN + n] == 0) {
        dv[0] = dv[1] = dv[2] = dv[3] = CUDART_INF_F;
    }

    float nx[4], ny[4], nz[4];
#pragma unroll
    for (int i = 0; i < 4; i++) {
        float4 p = g_c4[b * NN + j[i]];
        nx[i] = p.x; ny[i] = p.y; nz[i] = p.z;
    }

    // Channels [0..7]: normalized + relu conv output, float4 stores along K
    const size_t obase = ((size_t)b * (2 * DD)) * NN * KK + (size_t)n * KK + k0;
#pragma unroll
    for (int d = 0; d < DD; d++) {
        float4 o;
        float x0 = base[d] + wn0[d]*nx[0] + wn1[d]*ny[0] + wn2[d]*nz[0] + wdd[d]*dv[0];
        float x1 = base[d] + wn0[d]*nx[1] + wn1[d]*ny[1] + wn2[d]*nz[1] + wdd[d]*dv[1];
        float x2 = base[d] + wn0[d]*nx[2] + wn1[d]*ny[2] + wn2[d]*nz[2] + wdd[d]*dv[2];
        float x3 = base[d] + wn0[d]*nx[3] + wn1[d]*ny[3] + wn2[d]*nz[3] + wdd[d]*dv[3];
        o.x = fmaxf(fmaf(x0, scale[d], shift[d]), 0.f);
        o.y = fmaxf(fmaf(x1, scale[d], shift[d]), 0.f);
        o.z = fmaxf(fmaf(x2, scale[d], shift[d]), 0.f);
        o.w = fmaxf(fmaf(x3, scale[d], shift[d]), 0.f);
        *reinterpret_cast<float4*>(out + obase + (size_t)d * NN * KK) = o;
    }

    // Channels [8..15]: broadcast input features along K
#pragma unroll
    for (int d = 0; d < DD; d++) {
        float fv = features[((size_t)b * DD + d) * NN + n];
        float4 o = {fv, fv, fv, fv};
        *reinterpret_cast<float4*>(out + obase + (size_t)(DD + d) * NN * KK) = o;
    }
}

extern "C" void kernel_launch(void* const* d_in, const int* in_sizes, int n_in,
                              void* d_out, int out_size) {
    const float* coords   = (const float*)d_in[0];
    const float* features = (const float*)d_in[1];
    const int*   knn_idx  = (const int*)d_in[2];
    const float* knn_dist = (const float*)d_in[3];
    const int*   mask     = (const int*)d_in[4];
    const float* conv_w   = (const float*)d_in[5];
    const float* conv_b   = (const float*)d_in[6];
    const float* bn_gamma = (const float*)d_in[7];
    const float* bn_beta  = (const float*)d_in[8];
    float*       out      = (float*)d_out;

    k_repack<<<(BB * NN) / TPB, TPB>>>(coords);
    k_pass1_stats<<<NBLK, TPB>>>(coords, knn_idx, knn_dist, mask, conv_w, conv_b);
    k_pass2_write<<<NBLK, TPB>>>(coords, features, knn_idx, knn_dist, mask,
                                 conv_w, conv_b, bn_gamma, bn_beta, out);
}

// round 4
// speedup vs baseline: 1.5201x; 1.4359x over previous
#include <cuda_runtime.h>
#include <math_constants.h>

// Problem constants (fixed by the reference setup)
#define BB   4
#define NN   32768
#define KK   16
#define DD   8
#define TOT  (BB * NN * KK)        // 2,097,152 elements per channel
#define GRPS (TOT / 4)             // 524,288 groups of 4 (along K)
#define TPB  256
#define NBLK2 (GRPS / TPB)         // 2048 blocks for pass2
#define NBLK1 256                  // pass1 grid-stride blocks
#define ITERS1 (GRPS / (NBLK1 * TPB))  // 8 groups per pass1 thread
#define EPSF 1e-6f

// Global scratch (device globals: no allocation allowed)
__device__ double g_sum[DD];
__device__ double g_sqs[DD];
__device__ float  g_scale[DD];
__device__ float  g_shift[DD];
__device__ unsigned int g_ctr;
__device__ float4 g_c4[BB * NN];   // repacked coords, 2 MB (L2-resident)

__device__ __forceinline__ int clamp_idx(int v) {
    v = v < 0 ? 0 : v;
    return v >= NN ? NN - 1 : v;
}

// Repack (B,N,3) -> float4; 4 points per thread; also reset accumulators.
__global__ void __launch_bounds__(TPB) k_repack(const float* __restrict__ coords) {
    const int t = blockIdx.x * TPB + threadIdx.x;   // 0 .. BB*NN/4-1
    if (blockIdx.x == 0 && threadIdx.x < DD) {
        g_sum[threadIdx.x] = 0.0;
        g_sqs[threadIdx.x] = 0.0;
        if (threadIdx.x == 0) g_ctr = 0u;
    }
    // 4 points = 12 floats = 3 float4 coalesced-ish reads
    const float4* cin = reinterpret_cast<const float4*>(coords);
    float4 a = cin[3 * t + 0];
    float4 bq = cin[3 * t + 1];
    float4 cq = cin[3 * t + 2];
    g_c4[4 * t + 0] = make_float4(a.x, a.y, a.z, 0.f);
    g_c4[4 * t + 1] = make_float4(a.w, bq.x, bq.y, 0.f);
    g_c4[4 * t + 2] = make_float4(bq.z, bq.w, cq.x, 0.f);
    g_c4[4 * t + 3] = make_float4(cq.y, cq.z, cq.w, 0.f);
}

// Pass 1: grid-stride stats + last-block finalize of BN affine params.
__global__ void __launch_bounds__(TPB) k_pass1_stats(
    const int* __restrict__ knn_idx,       // (B,N,K) int32
    const float* __restrict__ knn_dist,    // (B,N,K)
    const int* __restrict__ mask,          // (B,N)
    const float* __restrict__ conv_w,      // (D,10)
    const float* __restrict__ conv_b,      // (D)
    const float* __restrict__ bn_gamma,
    const float* __restrict__ bn_beta)
{
    const int gid = blockIdx.x * TPB + threadIdx.x;

    // n-independent folded weights (hoisted out of the group loop)
    float wn0[DD], wn1[DD], wn2[DD], wdd[DD], wc0[DD], wc1[DD], wc2[DD], bb0[DD];
#pragma unroll
    for (int d = 0; d < DD; d++) {
        const float* w = conv_w + d * 10;
        float w0 = w[0], w1 = w[1], w2 = w[2];
        float w3 = w[3], w4 = w[4], w5 = w[5];
        float w6 = w[6], w7 = w[7], w8 = w[8];
        wn0[d] = w3 - w6; wn1[d] = w4 - w7; wn2[d] = w5 - w8;
        wdd[d] = w[9];
        wc0[d] = w0 + w6; wc1[d] = w1 + w7; wc2[d] = w2 + w8;
        bb0[d] = conv_b[d];
    }

    float s[DD], q[DD];
#pragma unroll
    for (int d = 0; d < DD; d++) { s[d] = 0.f; q[d] = 0.f; }

    for (int it = 0; it < ITERS1; it++) {
        const int g  = it * (NBLK1 * TPB) + gid;
        const int e0 = g * 4;
        const int b  = e0 / (NN * KK);
        const int rm = e0 - b * (NN * KK);
        const int n  = rm / KK;

        const float4 c = g_c4[b * NN + n];

        int4 iv = *reinterpret_cast<const int4*>(knn_idx + e0);
        int j0 = clamp_idx(iv.x), j1 = clamp_idx(iv.y);
        int j2 = clamp_idx(iv.z), j3 = clamp_idx(iv.w);

        float4 d4 = *reinterpret_cast<const float4*>(knn_dist + e0);
        float dv[4] = {d4.x, d4.y, d4.z, d4.w};
        if (mask[b * NN + n] == 0) {
            dv[0] = dv[1] = dv[2] = dv[3] = CUDART_INF_F;
        }

        float4 p0 = g_c4[b * NN + j0];
        float4 p1 = g_c4[b * NN + j1];
        float4 p2 = g_c4[b * NN + j2];
        float4 p3 = g_c4[b * NN + j3];
        float nx[4] = {p0.x, p1.x, p2.x, p3.x};
        float ny[4] = {p0.y, p1.y, p2.y, p3.y};
        float nz[4] = {p0.z, p1.z, p2.z, p3.z};

#pragma unroll
        for (int d = 0; d < DD; d++) {
            float base = bb0[d] + wc0[d] * c.x + wc1[d] * c.y + wc2[d] * c.z;
#pragma unroll
            for (int i = 0; i < 4; i++) {
                float x = base + wn0[d] * nx[i] + wn1[d] * ny[i]
                        + wn2[d] * nz[i] + wdd[d] * dv[i];
                s[d] += x;
                q[d] = fmaf(x, x, q[d]);
            }
        }
    }

    // Warp reduction, block partials, double atomics.
#pragma unroll
    for (int d = 0; d < DD; d++) {
#pragma unroll
        for (int o = 16; o > 0; o >>= 1) {
            s[d] += __shfl_xor_sync(0xFFFFFFFFu, s[d], o);
            q[d] += __shfl_xor_sync(0xFFFFFFFFu, q[d], o);
        }
    }

    __shared__ float sh[TPB / 32][2 * DD];
    __shared__ bool is_last;
    const int warp = threadIdx.x >> 5;
    const int lane = threadIdx.x & 31;
    if (lane == 0) {
#pragma unroll
        for (int d = 0; d < DD; d++) {
            sh[warp][d]      = s[d];
            sh[warp][DD + d] = q[d];
        }
    }
    __syncthreads();
    if (threadIdx.x < 2 * DD) {
        float acc = 0.f;
#pragma unroll
        for (int w = 0; w < TPB / 32; w++) acc += sh[w][threadIdx.x];
        if (threadIdx.x < DD)
            atomicAdd(&g_sum[threadIdx.x], (double)acc);
        else
            atomicAdd(&g_sqs[threadIdx.x - DD], (double)acc);
    }
    __syncthreads();
    if (threadIdx.x == 0) {
        __threadfence();
        unsigned int prev = atomicAdd(&g_ctr, 1u);
        is_last = (prev == (unsigned int)(NBLK1 - 1));
    }
    __syncthreads();
    if (is_last && threadIdx.x < DD) {
        const int d = threadIdx.x;
        double mean = g_sum[d] * (1.0 / (double)TOT);
        double var  = g_sqs[d] * (1.0 / (double)TOT) - mean * mean;
        float rstd  = rsqrtf((float)var + EPSF);
        float sc    = bn_gamma[d] * rstd;
        g_scale[d]  = sc;
        g_shift[d]  = bn_beta[d] - (float)mean * sc;
    }
}

// Pass 2: pure fp32, write the 128 MB output.
__global__ void __launch_bounds__(TPB) k_pass2_write(
    const float* __restrict__ features,    // (B,D,N,1)
    const int* __restrict__ knn_idx,
    const float* __restrict__ knn_dist,
    const int* __restrict__ mask,
    const float* __restrict__ conv_w,
    const float* __restrict__ conv_b,
    float* __restrict__ out)               // (B, 2D, N, K)
{
    const int g  = blockIdx.x * TPB + threadIdx.x;
    const int e0 = g * 4;
    const int b  = e0 / (NN * KK);
    const int rm = e0 - b * (NN * KK);
    const int n  = rm / KK;
    const int k0 = rm - n * KK;

    float scale[DD], shift[DD];
#pragma unroll
    for (int d = 0; d < DD; d++) {
        scale[d] = g_scale[d];
        shift[d] = g_shift[d];
    }

    const float4 c = g_c4[b * NN + n];

    float wn0[DD], wn1[DD], wn2[DD], wdd[DD], base[DD];
#pragma unroll
    for (int d = 0; d < DD; d++) {
        const float* w = conv_w + d * 10;
        float w0 = w[0], w1 = w[1], w2 = w[2];
        float w3 = w[3], w4 = w[4], w5 = w[5];
        float w6 = w[6], w7 = w[7], w8 = w[8];
        wn0[d] = w3 - w6; wn1[d] = w4 - w7; wn2[d] = w5 - w8;
        wdd[d] = w[9];
        base[d] = conv_b[d] + (w0 + w6) * c.x + (w1 + w7) * c.y + (w2 + w8) * c.z;
    }

    int4 iv = *reinterpret_cast<const int4*>(knn_idx + e0);
    int j0 = clamp_idx(iv.x), j1 = clamp_idx(iv.y);
    int j2 = clamp_idx(iv.z), j3 = clamp_idx(iv.w);

    float4 d4 = *reinterpret_cast<const float4*>(knn_dist + e0);
    float dv[4] = {d4.x, d4.y, d4.z, d4.w};
    if (mask[b * NN + n] == 0) {
        dv[0] = dv[1] = dv[2] = dv[3] = CUDART_INF_F;
    }

    float4 p0 = g_c4[b * NN + j0];
    float4 p1 = g_c4[b * NN + j1];
    float4 p2 = g_c4[b * NN + j2];
    float4 p3 = g_c4[b * NN + j3];
    float nx[4] = {p0.x, p1.x, p2.x, p3.x};
    float ny[4] = {p0.y, p1.y, p2.y, p3.y};
    float nz[4] = {p0.z, p1.z, p2.z, p3.z};

    // Channels [0..7]: normalized + relu conv output, float4 stores along K
    const size_t obase = ((size_t)b * (2 * DD)) * NN * KK + (size_t)n * KK + k0;
#pragma unroll
    for (int d = 0; d < DD; d++) {
        float x0 = base[d] + wn0[d]*nx[0] + wn1[d]*ny[0] + wn2[d]*nz[0] + wdd[d]*dv[0];
        float x1 = base[d] + wn0[d]*nx[1] + wn1[d]*ny[1] + wn2[d]*nz[1] + wdd[d]*dv[1];
        float x2 = base[d] + wn0[d]*nx[2] + wn1[d]*ny[2] + wn2[d]*nz[2] + wdd[d]*dv[2];
        float x3 = base[d] + wn0[d]*nx[3] + wn1[d]*ny[3] + wn2[d]*nz[3] + wdd[d]*dv[3];
        float4 o;
        o.x = fmaxf(fmaf(x0, scale[d], shift[d]), 0.f);
        o.y = fmaxf(fmaf(x1, scale[d], shift[d]), 0.f);
        o.z = fmaxf(fmaf(x2, scale[d], shift[d]), 0.f);
        o.w = fmaxf(fmaf(x3, scale[d], shift[d]), 0.f);
        *reinterpret_cast<float4*>(out + obase + (size_t)d * NN * KK) = o;
    }

    // Channels [8..15]: broadcast input features along K
#pragma unroll
    for (int d = 0; d < DD; d++) {
        float fv = features[((size_t)b * DD + d) * NN + n];
        float4 o = {fv, fv, fv, fv};
        *reinterpret_cast<float4*>(out + obase + (size_t)(DD + d) * NN * KK) = o;
    }
}

extern "C" void kernel_launch(void* const* d_in, const int* in_sizes, int n_in,
                              void* d_out, int out_size) {
    const float* coords   = (const float*)d_in[0];
    const float* features = (const float*)d_in[1];
    const int*   knn_idx  = (const int*)d_in[2];
    const float* knn_dist = (const float*)d_in[3];
    const int*   mask     = (const int*)d_in[4];
    const float* conv_w   = (const float*)d_in[5];
    const float* conv_b   = (const float*)d_in[6];
    const float* bn_gamma = (const float*)d_in[7];
    const float* bn_beta  = (const float*)d_in[8];
    float*       out      = (float*)d_out;

    k_repack<<<(BB * NN / 4) / TPB, TPB>>>(coords);
    k_pass1_stats<<<NBLK1, TPB>>>(knn_idx, knn_dist, mask, conv_w, conv_b,
                                  bn_gamma, bn_beta);
    k_pass2_write<<<NBLK2, TPB>>>(features, knn_idx, knn_dist, mask,
                                  conv_w, conv_b, out);
}